// round 16
// baseline (speedup 1.0000x reference)
#include <cuda_runtime.h>

#define B_TOT 4096
#define N_DIM 64
#define H_DIM 256
#define GB2   16                 // batch rows per fused block
#define FBLK  (B_TOT / GB2)      // 256 fused blocks
#define NCOL  320                // 256 Ws cols + 64 gate cols

// Precomputed tensors (static device globals — no runtime allocation)
__device__ float4 g_Bt4[64 * NCOL];        // 400 KB: K-major [W_w | h+w], Bt4[kq*320+c] = col c, k=4kq..4kq+3
__device__ float  g_A  [N_DIM * H_DIM];    //  64 KB: h@U^T + w@V^T

// ---------------------------------------------------------------------------
// Prep kernel: grid 352 x 256 threads.
//   bid < 320 : build Bt column c=bid (threads 0..63 write 64 k-quads)
//   bid >= 320: A blocks (32): each covers 8 A-columns, warp per column,
//               lane-parallel dot over H=256 (h@U^T) + 256 (w@V^T).
// ---------------------------------------------------------------------------
__global__ __launch_bounds__(256) void prep_kernel(
    const float* __restrict__ h_in, const float* __restrict__ w_in,
    const float* __restrict__ U_w, const float* __restrict__ V_w,
    const float* __restrict__ W_w)
{
    const int t   = threadIdx.x;
    const int bid = blockIdx.x;

    const float4* h4 = (const float4*)h_in;
    const float4* w4 = (const float4*)w_in;

    if (bid < NCOL) {
        // ---- transpose: Bt4[kq][c] for c = bid ----
        if (t < 64) {
            float4 v;
            if (bid < 256) {
                v = ((const float4*)W_w)[bid * 64 + t];
            } else {
                float4 a = h4[(bid - 256) * 64 + t];
                float4 b = w4[(bid - 256) * 64 + t];
                v = make_float4(a.x + b.x, a.y + b.y, a.z + b.z, a.w + b.w);
            }
            g_Bt4[t * NCOL + bid] = v;
        }
        return;
    }

    // ---- A blocks: block covers cols k0..k0+7, warp w owns col k0+w ----
    const int b2   = bid - NCOL;          // 0..31
    const int lane = t & 31;
    const int wid  = t >> 5;              // 0..7
    const int c    = b2 * 8 + wid;        // A column (0..255)

    const float4* U4 = (const float4*)U_w;
    const float4* V4 = (const float4*)V_w;

    float4 u0 = U4[c * 64 + lane];
    float4 u1 = U4[c * 64 + 32 + lane];
    float4 v0 = V4[c * 64 + lane];
    float4 v1 = V4[c * 64 + 32 + lane];

    #pragma unroll 2
    for (int n = 0; n < N_DIM; n++) {
        float4 a0 = h4[n * 64 + lane];
        float4 a1 = h4[n * 64 + 32 + lane];
        float4 b0 = w4[n * 64 + lane];
        float4 b1 = w4[n * 64 + 32 + lane];
        float s = 0.0f;
        s = fmaf(a0.x, u0.x, s); s = fmaf(a0.y, u0.y, s);
        s = fmaf(a0.z, u0.z, s); s = fmaf(a0.w, u0.w, s);
        s = fmaf(a1.x, u1.x, s); s = fmaf(a1.y, u1.y, s);
        s = fmaf(a1.z, u1.z, s); s = fmaf(a1.w, u1.w, s);
        s = fmaf(b0.x, v0.x, s); s = fmaf(b0.y, v0.y, s);
        s = fmaf(b0.z, v0.z, s); s = fmaf(b0.w, v0.w, s);
        s = fmaf(b1.x, v1.x, s); s = fmaf(b1.y, v1.y, s);
        s = fmaf(b1.z, v1.z, s); s = fmaf(b1.w, v1.w, s);
        #pragma unroll
        for (int off = 16; off > 0; off >>= 1)
            s += __shfl_xor_sync(0xffffffffu, s, off);
        if (lane == 0) g_A[n * H_DIM + c] = s;
    }
}

// ---------------------------------------------------------------------------
// Fused kernel: grid 256 x 320 threads, block owns 16 batch rows.
//  Phase 1: stage s rows in smem.
//  Phase 2: thread t = output col t of [Ws | gate] (coalesced Bt reads,
//           broadcast s LDS), acc[16] over K=256; results -> smem.
//  Phase 3: ew-style epilogue (warps 0..7), stores straight from smem.
// ---------------------------------------------------------------------------
__global__ __launch_bounds__(NCOL, 3) void fused_kernel(
    const float* __restrict__ s_t, const float* __restrict__ h_in,
    const float* __restrict__ prelu_a, float* __restrict__ out)
{
    __shared__ float4 s4[GB2][64];        // 16 KB  s rows
    __shared__ float  ws[GB2][H_DIM];     // 16 KB  Ws rows
    __shared__ float  gs[GB2][N_DIM];     //  4 KB  gates

    const int t  = threadIdx.x;
    const int b0 = blockIdx.x * GB2;

    // ---- Phase 1: load s rows ----
    const float4* st4 = (const float4*)s_t;
    for (int f = t; f < GB2 * 64; f += NCOL) {
        int b = f >> 6, kq = f & 63;
        s4[b][kq] = st4[(b0 + b) * 64 + kq];
    }
    __syncthreads();

    // ---- Phase 2: GEMM, one col per thread ----
    {
        float acc[GB2];
        #pragma unroll
        for (int r = 0; r < GB2; r++) acc[r] = 0.0f;

        #pragma unroll 1
        for (int kq = 0; kq < 64; kq++) {
            float4 bv = g_Bt4[kq * NCOL + t];
            #pragma unroll
            for (int r = 0; r < GB2; r++) {
                float4 sv = s4[r][kq];
                float a = acc[r];
                a = fmaf(sv.x, bv.x, a); a = fmaf(sv.y, bv.y, a);
                a = fmaf(sv.z, bv.z, a); a = fmaf(sv.w, bv.w, a);
                acc[r] = a;
            }
        }

        if (t < 256) {
            #pragma unroll
            for (int r = 0; r < GB2; r++) ws[r][t] = acc[r];
        } else {
            int n = t - 256;
            #pragma unroll
            for (int r = 0; r < GB2; r++)
                gs[r][n] = 1.0f / (1.0f + __expf(-acc[r]));
        }
    }
    __syncthreads();

    // ---- Phase 3: epilogue (warps 0..7) ----
    if (t < 256) {
        const int lane = t & 31;
        const int wid  = t >> 5;

        const float   a0 = prelu_a[0];
        const float4* A4 = (const float4*)g_A;
        const float4* h4 = (const float4*)h_in;
        float4*       o4 = (float4*)out;

        #pragma unroll 1
        for (int i = 0; i < 8; i++) {
            int n = wid * 8 + i;
            float4 Aa = A4[n * 64 + lane];
            float4 Ab = A4[n * 64 + 32 + lane];
            float4 ha = h4[n * 64 + lane];
            float4 hb = h4[n * 64 + 32 + lane];

            #pragma unroll
            for (int g = 0; g < GB2; g++) {
                const float4* wsr = (const float4*)ws[g];
                float4 wa = wsr[lane];
                float4 wb = wsr[32 + lane];
                float  gv = gs[g][n];

                float v0, v1, v2, v3, v4v, v5, v6, v7;
                float ss0 = 0.0f, ss1 = 0.0f;
                #define COMP(vv, sacc, Ae, we, he)                           \
                    {                                                        \
                        float x = (Ae) + (we);                               \
                        float c = fmaxf(x, 0.0f) + a0 * fminf(x, 0.0f);      \
                        vv = fmaf(gv, c, (he));                              \
                        sacc = fmaf(vv, vv, sacc);                           \
                    }
                COMP(v0,  ss0, Aa.x, wa.x, ha.x)
                COMP(v1,  ss1, Aa.y, wa.y, ha.y)
                COMP(v2,  ss0, Aa.z, wa.z, ha.z)
                COMP(v3,  ss1, Aa.w, wa.w, ha.w)
                COMP(v4v, ss0, Ab.x, wb.x, hb.x)
                COMP(v5,  ss1, Ab.y, wb.y, hb.y)
                COMP(v6,  ss0, Ab.z, wb.z, hb.z)
                COMP(v7,  ss1, Ab.w, wb.w, hb.w)
                #undef COMP

                float ss = ss0 + ss1;
                #pragma unroll
                for (int off = 16; off > 0; off >>= 1)
                    ss += __shfl_xor_sync(0xffffffffu, ss, off);
                float inv = rsqrtf(ss);

                long base = ((long)(b0 + g) * N_DIM + n) * 64;
                o4[base + lane]      = make_float4(v0 * inv,  v1 * inv, v2 * inv, v3 * inv);
                o4[base + 32 + lane] = make_float4(v4v * inv, v5 * inv, v6 * inv, v7 * inv);
            }
        }
    }
}

// ---------------------------------------------------------------------------
extern "C" void kernel_launch(void* const* d_in, const int* in_sizes, int n_in,
                              void* d_out, int out_size)
{
    const float* s_t     = (const float*)d_in[0];   // [4096,256]
    const float* h_in    = (const float*)d_in[1];   // [1,64,256]
    const float* w_in    = (const float*)d_in[2];   // [1,64,256]
    const float* U_w     = (const float*)d_in[3];   // [256,256]
    const float* V_w     = (const float*)d_in[4];   // [256,256]
    const float* W_w     = (const float*)d_in[5];   // [256,256]
    const float* prelu_a = (const float*)d_in[6];   // [1]
    float*       out     = (float*)d_out;           // [4096,64,256]

    prep_kernel<<<NCOL + 32, 256>>>(h_in, w_in, U_w, V_w, W_w);
    fused_kernel<<<FBLK, NCOL>>>(s_t, h_in, prelu_a, out);
}